// round 5
// baseline (speedup 1.0000x reference)
#include <cuda_runtime.h>
#include <cuda_fp16.h>
#include <cstdint>

// Problem constants
#define B_  32
#define T_  1000
#define I_  3
#define R_  2048
#define O_  3

#define CAP     160          // per-row nnz capacity (padded to mult of 16)
#define GRID    128          // persistent CTAs (all co-resident)
#define RPC     16           // rows per CTA
#define NTHR    512          // 16 warps, warp-per-row
#define D_      16           // state ring depth (skew bound ~3 << 15)

// ---------------- device scratch ----------------
__device__ __half            g_state[D_][R_ * B_];    // fp16 state ring, [r][b]
__device__ float             g_final[R_ * B_];        // fp32 final state for outproj
__device__ unsigned          g_cols[R_][CAP];         // col * 16 (uint-word offset of row)
__device__ float             g_vals[R_][CAP];
__device__ int               g_cnt[R_];               // padded to multiple of 16, >=16
__device__ unsigned          g_flagR[R_ * 32];        // per-row flag, one 128B line each

// ---------------- helpers ----------------
__device__ __forceinline__ unsigned ld_acq(const unsigned* p) {
    unsigned v;
    asm volatile("ld.acquire.gpu.u32 %0, [%1];" : "=r"(v) : "l"(p) : "memory");
    return v;
}
__device__ __forceinline__ void st_rel(unsigned* p, unsigned v) {
    asm volatile("st.release.gpu.u32 [%0], %1;" :: "l"(p), "r"(v) : "memory");
}

// ---------------- P1: sparse compaction + init ----------------
__global__ void prep_kernel(const float* __restrict__ W) {
    int r = blockIdx.x;
    int lane = threadIdx.x;
    const float* row = W + (size_t)r * R_;

    int base = 0;
    for (int c0 = 0; c0 < R_; c0 += 32) {
        float v = row[c0 + lane];
        unsigned m = __ballot_sync(0xffffffffu, v != 0.0f);
        if (v != 0.0f) {
            int off = __popc(m & ((1u << lane) - 1u));
            int p = base + off;
            if (p < CAP) {
                g_cols[r][p] = (unsigned)(c0 + lane) * 16u;   // uint words per fp16 row
                g_vals[r][p] = v;
            }
        }
        base += __popc(m);
    }
    if (base > CAP) base = CAP;
    int padded = (base + 15) & ~15;
    if (padded < 16) padded = 16;
    if (padded > CAP) padded = CAP;
    for (int p = base + lane; p < padded; p += 32) {
        g_cols[r][p] = ((unsigned)(r * 7 + p * 13) & (R_ - 1)) * 16u;
        g_vals[r][p] = 0.0f;
    }
    if (lane == 0) g_cnt[r] = padded;

    // reset per-launch mutable state (graph replay safe)
    g_state[0][r * B_ + lane] = __float2half(0.0f);
    if (lane == 0) g_flagR[r << 5] = 0u;   // state_0 ready
}

// ---------------- P2: persistent recurrence (warp-level dataflow) ----------------
__global__ void __launch_bounds__(NTHR, 1)
esn_kernel(const float* __restrict__ x,        // [B,T,I]
           const float* __restrict__ win,      // [R,I]
           const float* __restrict__ noise,    // [B,R]
           float* __restrict__ states_out) {   // [B,T,R]
    __shared__ uint2 snnz[RPC][CAP];           // (col*16, val bits)  20 KB

    const int tid  = threadIdx.x;
    const int w    = tid >> 5;                 // warp = local row
    const int lane = tid & 31;
    const int hsel = lane >> 4;                // 0: even nnz, 1: odd nnz
    const int hl   = lane & 15;                // half-lane -> batch pair (2hl, 2hl+1)
    const int b0   = hl << 1;
    const int b1   = b0 + 1;
    const int r    = blockIdx.x * RPC + w;

    // preload sparse row into SMEM (warp-local, reused for all 1000 steps)
    const int cnt = g_cnt[r];
    for (int k = lane; k < cnt; k += 32)
        snnz[w][k] = make_uint2(g_cols[r][k], __float_as_uint(g_vals[r][k]));
    __syncwarp();

    // per-thread constants (2 batches per thread)
    const float nz0 = noise[(size_t)b0 * R_ + r];
    const float nz1 = noise[(size_t)b1 * R_ + r];
    const float w0 = win[r * 3 + 0];
    const float w1 = win[r * 3 + 1];
    const float w2 = win[r * 3 + 2];

    const int npairs = cnt >> 1;               // LDG pairs per row (multiple of 8)

    for (int t = 0; t < T_; t++) {
        const unsigned* cur = (const unsigned*)&g_state[t & (D_ - 1)][0];
        __half2* nxt        = (__half2*)&g_state[(t + 1) & (D_ - 1)][0];

        // ---- input term (x immutable -> L1-cached, shared by all warps) ----
        float ax = 0.0f, ay = 0.0f;
        if (hsel == 0) {
            const float* xb0 = x + (size_t)b0 * (T_ * I_) + t * I_;
            const float* xb1 = x + (size_t)b1 * (T_ * I_) + t * I_;
            ax = fmaf(w0, __ldg(xb0),  fmaf(w1, __ldg(xb0 + 1), fmaf(w2, __ldg(xb0 + 2), nz0)));
            ay = fmaf(w0, __ldg(xb1),  fmaf(w1, __ldg(xb1 + 1), fmaf(w2, __ldg(xb1 + 2), nz1)));
        }

        // ---- wait for dependency flags (lane k checks deps k, k+32, ...) ----
        for (int k = lane; k < cnt; k += 32) {
            const unsigned* fp = &g_flagR[snnz[w][k].x << 1];  // (col*16)*2 = col*32
            while (ld_acq(fp) < (unsigned)t) { }
        }
        __syncwarp();

        float accx = ax, accy = ay;

        // ---- software-pipelined gather: 8 LDGs/chunk, each LDG covers 2 nnz ----
        unsigned sA[8]; float vA[8];
        unsigned sB[8]; float vB[8];

        auto load8 = [&](unsigned* s, float* v, int pbase) {
            #pragma unroll
            for (int j = 0; j < 8; j++) {
                uint2 e = snnz[w][((pbase + j) << 1) + hsel];
                v[j] = __uint_as_float(e.y);
                s[j] = __ldcg(cur + e.x + hl);     // L2-only, 4B = 2 fp16 batches
            }
        };
        auto consume8 = [&](const unsigned* s, const float* v) {
            #pragma unroll
            for (int j = 0; j < 8; j++) {
                float2 f = __half22float2(*(const __half2*)&s[j]);
                accx = fmaf(v[j], f.x, accx);
                accy = fmaf(v[j], f.y, accy);
            }
        };

        load8(sA, vA, 0);
        for (int p = 8; p < npairs; p += 16) {
            load8(sB, vB, p);
            consume8(sA, vA);
            if (p + 8 < npairs) load8(sA, vA, p + 8);
            consume8(sB, vB);
        }
        if ((npairs >> 3) & 1) consume8(sA, vA);

        // merge even/odd halves (lanes L and L+16 hold partials for same batches)
        accx += __shfl_xor_sync(0xffffffffu, accx, 16);
        accy += __shfl_xor_sync(0xffffffffu, accy, 16);

        // one tanh per lane: hsel0 -> batch b0, hsel1 -> batch b1
        float sv = tanhf(hsel == 0 ? accx : accy);
        float sp = __shfl_xor_sync(0xffffffffu, sv, 16);   // partner's value

        if (hsel == 0) {
            nxt[r * (B_ / 2) + hl] = __floats2half2_rn(sv, sp);   // 64B coalesced
            if (t == T_ - 1) {
                g_final[r * B_ + b0] = sv;
                g_final[r * B_ + b1] = sp;
            }
        }
        __syncwarp();   // all 16 state stores issued

        // ---- publish: drain state stores, raise this row's flag ----
        if (lane == 0) {
            __threadfence();
            st_rel(&g_flagR[r << 5], (unsigned)(t + 1));
        }

        // ---- off critical path: scattered states_out write (fire & forget) ----
        {
            int bb = (hsel == 0) ? b0 : b1;
            states_out[(size_t)bb * (T_ * R_) + (size_t)t * R_ + r] = sv;
        }
    }
}

// ---------------- P3: output projection ----------------
__global__ void outproj_kernel(const float* __restrict__ wout,  // [O,R]
                               float* __restrict__ out) {       // [B*O]
    __shared__ float red[256];
    int pair = blockIdx.x;            // 0..95
    int b = pair / O_, o = pair - b * O_;

    float sum = 0.0f;
    for (int r = threadIdx.x; r < R_; r += blockDim.x)
        sum += g_final[r * B_ + b] * wout[o * R_ + r];

    red[threadIdx.x] = sum;
    __syncthreads();
    for (int s = 128; s > 0; s >>= 1) {
        if (threadIdx.x < s) red[threadIdx.x] += red[threadIdx.x + s];
        __syncthreads();
    }
    if (threadIdx.x == 0) out[b * O_ + o] = red[0];
}

// ---------------- launch ----------------
extern "C" void kernel_launch(void* const* d_in, const int* in_sizes, int n_in,
                              void* d_out, int out_size) {
    (void)in_sizes; (void)n_in; (void)out_size;
    const float* x     = (const float*)d_in[0];   // [B,T,I]
    const float* win   = (const float*)d_in[1];   // [R,I]
    const float* wres  = (const float*)d_in[2];   // [R,R]
    const float* wout  = (const float*)d_in[3];   // [O,R]
    const float* noise = (const float*)d_in[4];   // [B,R]
    float* out = (float*)d_out;                   // [B*O] then [B,T,R]

    prep_kernel<<<R_, 32>>>(wres);
    esn_kernel<<<GRID, NTHR>>>(x, win, noise, out + B_ * O_);
    outproj_kernel<<<B_ * O_, 256>>>(wout, out);
}

// round 6
// speedup vs baseline: 2.0196x; 2.0196x over previous
#include <cuda_runtime.h>
#include <cuda_fp16.h>
#include <cstdint>

// Problem constants
#define B_  32
#define T_  1000
#define I_  3
#define R_  2048
#define O_  3

#define CAP     160          // per-row nnz capacity (padded to mult of 16)
#define GRID    128          // persistent CTAs (all co-resident)
#define RPC     16           // rows per CTA
#define NTHR    512          // 16 warps, warp-per-row

// ---------------- device scratch ----------------
__device__ __half            g_state[2][R_ * B_];     // fp16 state, [r][b], 64B/row
__device__ float             g_st32[2][R_ * B_];      // fp32 states ring for output path
__device__ unsigned          g_cols[R_][CAP];         // col * 16 (uint-word offset of fp16 row)
__device__ float             g_vals[R_][CAP];
__device__ int               g_cnt[R_];               // padded to multiple of 16, >=16
__device__ int               g_asn[R_];               // balanced (cta,slot) -> row map
__device__ unsigned          g_flag[GRID * 32];       // one 128B line per CTA

// ---------------- helpers ----------------
__device__ __forceinline__ unsigned ld_acq(const unsigned* p) {
    unsigned v;
    asm volatile("ld.acquire.gpu.u32 %0, [%1];" : "=r"(v) : "l"(p) : "memory");
    return v;
}
__device__ __forceinline__ void st_rel(unsigned* p, unsigned v) {
    asm volatile("st.release.gpu.u32 [%0], %1;" :: "l"(p), "r"(v) : "memory");
}
__device__ __forceinline__ float tanh_fast(float x) {
    float y;
    asm("tanh.approx.f32 %0, %1;" : "=f"(y) : "f"(x));
    return y;
}

// ---------------- P1: sparse compaction + init ----------------
__global__ void prep_kernel(const float* __restrict__ W) {
    int r = blockIdx.x;
    int lane = threadIdx.x;
    const float* row = W + (size_t)r * R_;

    int base = 0;
    for (int c0 = 0; c0 < R_; c0 += 32) {
        float v = row[c0 + lane];
        unsigned m = __ballot_sync(0xffffffffu, v != 0.0f);
        if (v != 0.0f) {
            int off = __popc(m & ((1u << lane) - 1u));
            int p = base + off;
            if (p < CAP) {
                g_cols[r][p] = (unsigned)(c0 + lane) * 16u;   // uint words per fp16 row
                g_vals[r][p] = v;
            }
        }
        base += __popc(m);
    }
    if (base > CAP) base = CAP;
    int padded = (base + 15) & ~15;
    if (padded < 16) padded = 16;
    if (padded > CAP) padded = CAP;
    for (int p = base + lane; p < padded; p += 32) {
        g_cols[r][p] = ((unsigned)(r * 7 + p * 13) & (R_ - 1)) * 16u;
        g_vals[r][p] = 0.0f;
    }
    if (lane == 0) g_cnt[r] = padded;

    // reset per-launch mutable state (graph replay safe)
    g_state[0][r * B_ + lane] = __float2half(0.0f);
    if (r < GRID && lane == 0) g_flag[r << 5] = 0u;
}

// ---------------- P1b: balanced row->CTA assignment (counting sort + snake)
__global__ void assign_kernel() {
    __shared__ int scnt[R_];
    __shared__ int sasn[R_];
    int tid = threadIdx.x;
    for (int r = tid; r < R_; r += 1024) scnt[r] = g_cnt[r];
    __syncthreads();
    if (tid == 0) {
        int hist[CAP + 1];
        for (int i = 0; i <= CAP; i++) hist[i] = 0;
        for (int r = 0; r < R_; r++) hist[scnt[r]]++;
        int off[CAP + 1];
        int acc = 0;
        for (int c = CAP; c >= 0; c--) { off[c] = acc; acc += hist[c]; }  // desc by cnt
        for (int r = 0; r < R_; r++) {                                    // stable in r
            int p = off[scnt[r]]++;
            int round = p >> 7, pos = p & 127;
            int cta = (round & 1) ? (127 - pos) : pos;                    // snake
            sasn[cta * RPC + round] = r;
        }
    }
    __syncthreads();
    for (int i = tid; i < R_; i += 1024) g_asn[i] = sasn[i];
}

// ---------------- P2: persistent recurrence ----------------
__global__ void __launch_bounds__(NTHR, 1)
esn_kernel(const float* __restrict__ x,        // [B,T,I]
           const float* __restrict__ win,      // [R,I]
           const float* __restrict__ noise,    // [B,R]
           float* __restrict__ states_out) {   // [B,T,R]
    __shared__ uint2 snnz[RPC][CAP];           // (col*16, val bits)  20 KB
    __shared__ float tile[RPC][B_ + 1];        // bounce buffer for transposed out
    __shared__ float xs[B_][4];                // x_t per batch

    const int tid  = threadIdx.x;
    const int w    = tid >> 5;                 // warp = local row slot
    const int lane = tid & 31;
    const int hsel = lane >> 4;                // 0: even nnz, 1: odd nnz
    const int hl   = lane & 15;                // half-lane -> batch pair (2hl, 2hl+1)
    const int b0   = hl << 1;
    const int b1   = b0 + 1;
    const int rb16 = blockIdx.x * RPC;         // contiguous output row block
    const int r    = g_asn[rb16 + w];          // balanced compute row

    // indices for the output-path bounce (thread -> (rr, bL))
    const int rr = tid >> 5;                   // 0..15
    const int bL = tid & 31;

    // preload sparse row into SMEM (reused for all 1000 steps)
    const int cnt = g_cnt[r];
    for (int k = lane; k < cnt; k += 32)
        snnz[w][k] = make_uint2(g_cols[r][k], __float_as_uint(g_vals[r][k]));

    // per-thread constants (2 batches per thread)
    const float nz0 = noise[(size_t)b0 * R_ + r];
    const float nz1 = noise[(size_t)b1 * R_ + r];
    const float w0 = win[r * 3 + 0];
    const float w1 = win[r * 3 + 1];
    const float w2 = win[r * 3 + 2];

    // stage x for t=0
    if (tid < B_ * I_) {
        int b = tid / 3, i = tid - b * 3;
        xs[b][i] = x[(size_t)b * (T_ * I_) + i];
    }
    __syncthreads();

    const int npairs = cnt >> 1;               // LDGs per row (multiple of 8)

    for (int t = 0; t < T_; t++) {
        const unsigned* cur = (const unsigned*)&g_state[t & 1][0];
        __half2* nxt        = (__half2*)&g_state[(t + 1) & 1][0];

        // A: early LDG of states[t-1] fp32 (contiguous block rb16..rb16+15)
        //    garbage at t=0, discarded below.
        float tin = __ldcg(&g_st32[t & 1][(rb16 + rr) * B_ + bL]);

        // B: input term + gather
        float ax = fmaf(w0, xs[b0][0], fmaf(w1, xs[b0][1], fmaf(w2, xs[b0][2], nz0)));
        float ay = fmaf(w0, xs[b1][0], fmaf(w1, xs[b1][1], fmaf(w2, xs[b1][2], nz1)));
        float accx = (hsel == 0) ? ax : 0.0f;
        float accy = (hsel == 0) ? ay : 0.0f;

        unsigned sA[8]; float vA[8];
        unsigned sB[8]; float vB[8];

        auto load8 = [&](unsigned* s, float* v, int pbase) {
            #pragma unroll
            for (int j = 0; j < 8; j++) {
                uint2 e = snnz[w][((pbase + j) << 1) + hsel];
                v[j] = __uint_as_float(e.y);
                s[j] = __ldcg(cur + e.x + hl);     // L2-only, 4B = 2 fp16 batches
            }
        };
        auto consume8 = [&](const unsigned* s, const float* v) {
            #pragma unroll
            for (int j = 0; j < 8; j++) {
                float2 f = __half22float2(*(const __half2*)&s[j]);
                accx = fmaf(v[j], f.x, accx);
                accy = fmaf(v[j], f.y, accy);
            }
        };

        load8(sA, vA, 0);
        for (int p = 8; p < npairs; p += 16) {
            load8(sB, vB, p);
            consume8(sA, vA);
            if (p + 8 < npairs) load8(sA, vA, p + 8);
            consume8(sB, vB);
        }
        if ((npairs >> 3) & 1) consume8(sA, vA);

        // merge even/odd halves (lanes L and L+16 hold partials for same batches)
        accx += __shfl_xor_sync(0xffffffffu, accx, 16);
        accy += __shfl_xor_sync(0xffffffffu, accy, 16);

        float sv = tanh_fast(hsel == 0 ? accx : accy);
        float sp = __shfl_xor_sync(0xffffffffu, sv, 16);   // partner's value

        // C: state stores
        if (hsel == 0) {
            nxt[r * (B_ / 2) + hl] = __floats2half2_rn(sv, sp);            // 64B line
            ((float2*)&g_st32[(t + 1) & 1][r * B_])[hl] = make_float2(sv, sp); // 128B line
        }

        // D: bounce states[t-1] into smem tile
        tile[rr][bL] = tin;
        __syncthreads();                         // all STG + STS done, CTA-wide

        // arrival: release orders all prior stores (cumulative via bar.sync)
        if (tid == 0) st_rel(&g_flag[blockIdx.x << 5], (unsigned)(t + 1));

        // E: off-critical-path
        if (t >= 1) {   // transposed write of states[t-1], 64B per half-warp
            int b  = w + ((lane >> 4) << 4);
            int r2 = lane & 15;
            states_out[(size_t)b * (T_ * R_) + (size_t)(t - 1) * R_ + rb16 + r2] = tile[r2][b];
        }
        if (t + 1 < T_ && tid < B_ * I_) {       // stage x for t+1
            int b = tid / 3, i = tid - b * 3;
            xs[b][i] = x[(size_t)b * (T_ * I_) + (t + 1) * I_ + i];
        }

        // F: wait: 128 threads poll 128 distinct flag lines
        if (tid < GRID) {
            while (ld_acq(&g_flag[tid << 5]) < (unsigned)(t + 1)) { }
        }
        __syncthreads();
    }

    // epilogue: write states[T-1] (sits in g_st32[0], complete after final poll)
    float tin = __ldcg(&g_st32[0][(rb16 + rr) * B_ + bL]);
    tile[rr][bL] = tin;
    __syncthreads();
    {
        int b  = w + ((lane >> 4) << 4);
        int r2 = lane & 15;
        states_out[(size_t)b * (T_ * R_) + (size_t)(T_ - 1) * R_ + rb16 + r2] = tile[r2][b];
    }
}

// ---------------- P3: output projection ----------------
__global__ void outproj_kernel(const float* __restrict__ wout,  // [O,R]
                               float* __restrict__ out) {       // [B*O]
    __shared__ float red[256];
    int pair = blockIdx.x;            // 0..95
    int b = pair / O_, o = pair - b * O_;

    float sum = 0.0f;
    for (int r = threadIdx.x; r < R_; r += blockDim.x)
        sum += g_st32[0][r * B_ + b] * wout[o * R_ + r];   // states[999] in ring buf 0

    red[threadIdx.x] = sum;
    __syncthreads();
    for (int s = 128; s > 0; s >>= 1) {
        if (threadIdx.x < s) red[threadIdx.x] += red[threadIdx.x + s];
        __syncthreads();
    }
    if (threadIdx.x == 0) out[b * O_ + o] = red[0];
}

// ---------------- launch ----------------
extern "C" void kernel_launch(void* const* d_in, const int* in_sizes, int n_in,
                              void* d_out, int out_size) {
    (void)in_sizes; (void)n_in; (void)out_size;
    const float* x     = (const float*)d_in[0];   // [B,T,I]
    const float* win   = (const float*)d_in[1];   // [R,I]
    const float* wres  = (const float*)d_in[2];   // [R,R]
    const float* wout  = (const float*)d_in[3];   // [O,R]
    const float* noise = (const float*)d_in[4];   // [B,R]
    float* out = (float*)d_out;                   // [B*O] then [B,T,R]

    prep_kernel<<<R_, 32>>>(wres);
    assign_kernel<<<1, 1024>>>();
    esn_kernel<<<GRID, NTHR>>>(x, win, noise, out + B_ * O_);
    outproj_kernel<<<B_ * O_, 256>>>(wout, out);
}

// round 7
// speedup vs baseline: 2.0704x; 1.0251x over previous
#include <cuda_runtime.h>
#include <cuda_fp16.h>
#include <cstdint>

// Problem constants
#define B_  32
#define T_  1000
#define I_  3
#define R_  2048
#define O_  3

#define CAP     160          // per-row nnz capacity (padded to mult of 16)
#define GRID    128          // persistent CTAs (all co-resident)
#define RPC     16           // rows per CTA
#define NTHR    512          // 16 warps, warp-per-row
#define XBLK    32           // x staging window (steps)

// ---------------- device scratch ----------------
__device__ __half            g_state[2][R_ * B_];     // fp16 state, [r][b], 64B/row
__device__ float             g_final[R_ * B_];        // fp32 final state for outproj
__device__ unsigned          g_cols[R_][CAP];         // col * 16 (uint-word offset of fp16 row)
__device__ float             g_vals[R_][CAP];
__device__ int               g_cnt[R_];               // padded to multiple of 16, >=16
__device__ unsigned          g_flag[GRID * 32];       // one 128B line per CTA

// ---------------- helpers ----------------
__device__ __forceinline__ unsigned ld_acq(const unsigned* p) {
    unsigned v;
    asm volatile("ld.acquire.gpu.u32 %0, [%1];" : "=r"(v) : "l"(p) : "memory");
    return v;
}
__device__ __forceinline__ void st_rel(unsigned* p, unsigned v) {
    asm volatile("st.release.gpu.u32 [%0], %1;" :: "l"(p), "r"(v) : "memory");
}
__device__ __forceinline__ float tanh_fast(float x) {
    float y;
    asm("tanh.approx.f32 %0, %1;" : "=f"(y) : "f"(x));
    return y;
}

// ---------------- P1: sparse compaction + init ----------------
__global__ void prep_kernel(const float* __restrict__ W) {
    int r = blockIdx.x;
    int lane = threadIdx.x;
    const float* row = W + (size_t)r * R_;

    int base = 0;
    for (int c0 = 0; c0 < R_; c0 += 32) {
        float v = row[c0 + lane];
        unsigned m = __ballot_sync(0xffffffffu, v != 0.0f);
        if (v != 0.0f) {
            int off = __popc(m & ((1u << lane) - 1u));
            int p = base + off;
            if (p < CAP) {
                g_cols[r][p] = (unsigned)(c0 + lane) * 16u;   // uint words per fp16 row
                g_vals[r][p] = v;
            }
        }
        base += __popc(m);
    }
    if (base > CAP) base = CAP;
    int padded = (base + 15) & ~15;
    if (padded < 16) padded = 16;
    if (padded > CAP) padded = CAP;
    for (int p = base + lane; p < padded; p += 32) {
        g_cols[r][p] = ((unsigned)(r * 7 + p * 13) & (R_ - 1)) * 16u;
        g_vals[r][p] = 0.0f;
    }
    if (lane == 0) g_cnt[r] = padded;

    // reset per-launch mutable state (graph replay safe)
    g_state[0][r * B_ + lane] = __float2half(0.0f);
    if (r < GRID && lane == 0) g_flag[r << 5] = 0u;
}

// ---------------- P2: persistent recurrence ----------------
__global__ void __launch_bounds__(NTHR, 1)
esn_kernel(const float* __restrict__ x,        // [B,T,I]
           const float* __restrict__ win,      // [R,I]
           const float* __restrict__ noise,    // [B,R]
           float* __restrict__ states_out) {   // [B,T,R]
    __shared__ uint2 snnz[RPC][CAP];           // (col*16, val bits)  20 KB
    __shared__ float tile[RPC][B_ + 1];        // staged fp32 outputs for transpose
    __shared__ float xs[XBLK][B_][4];          // 32-step x window, 16 KB

    const int tid  = threadIdx.x;
    const int w    = tid >> 5;                 // warp = local row
    const int lane = tid & 31;
    const int hsel = lane >> 4;                // 0: even nnz, 1: odd nnz
    const int hl   = lane & 15;                // half-lane -> batch pair (2hl, 2hl+1)
    const int b0   = hl << 1;
    const int b1   = b0 + 1;
    const int rbase = blockIdx.x * RPC;
    const int r = rbase + w;

    // preload sparse row into SMEM (reused for all 1000 steps)
    const int cnt = g_cnt[r];
    for (int k = lane; k < cnt; k += 32)
        snnz[w][k] = make_uint2(g_cols[r][k], __float_as_uint(g_vals[r][k]));

    // per-thread constants (2 batches per thread)
    const float nz0 = noise[(size_t)b0 * R_ + r];
    const float nz1 = noise[(size_t)b1 * R_ + r];
    const float w0 = win[r * 3 + 0];
    const float w1 = win[r * 3 + 1];
    const float w2 = win[r * 3 + 2];

    // x window refill: 3072 floats, 6 per thread, coalesced-ish
    auto refill_x = [&](int t0) {
        for (int g = tid; g < XBLK * B_ * I_; g += NTHR) {
            int b = g / (XBLK * I_);
            int rem = g - b * (XBLK * I_);
            int tp = rem / I_, i = rem - tp * I_;
            float v = (t0 + tp < T_) ? __ldg(&x[(size_t)b * (T_ * I_) + (t0 + tp) * I_ + i])
                                     : 0.0f;
            xs[tp][b][i] = v;
        }
    };
    refill_x(0);
    __syncthreads();

    const int npairs = cnt >> 1;               // LDG pairs per row (multiple of 8)

    for (int t = 0; t < T_; t++) {
        const unsigned* cur = (const unsigned*)&g_state[t & 1][0];
        __half2* nxt        = (__half2*)&g_state[(t + 1) & 1][0];
        const int tw = t & (XBLK - 1);

        float ax = fmaf(w0, xs[tw][b0][0], fmaf(w1, xs[tw][b0][1], fmaf(w2, xs[tw][b0][2], nz0)));
        float ay = fmaf(w0, xs[tw][b1][0], fmaf(w1, xs[tw][b1][1], fmaf(w2, xs[tw][b1][2], nz1)));
        // split across even/odd halves: recurrent accum starts at 0 on odd half
        float accx0 = (hsel == 0) ? ax : 0.0f, accx1 = 0.0f;
        float accy0 = (hsel == 0) ? ay : 0.0f, accy1 = 0.0f;

        // ---- software-pipelined gather: 8 LDGs/chunk, each LDG covers 2 nnz ----
        unsigned sA[8]; float vA[8];
        unsigned sB[8]; float vB[8];

        auto load8 = [&](unsigned* s, float* v, int pbase) {
            #pragma unroll
            for (int j = 0; j < 8; j++) {
                uint2 e = snnz[w][((pbase + j) << 1) + hsel];
                v[j] = __uint_as_float(e.y);
                s[j] = __ldcg(cur + e.x + hl);     // L2-only, 4B = 2 fp16 batches
            }
        };
        auto consume8 = [&](const unsigned* s, const float* v) {
            #pragma unroll
            for (int j = 0; j < 8; j += 2) {
                float2 f0 = __half22float2(*(const __half2*)&s[j]);
                float2 f1 = __half22float2(*(const __half2*)&s[j + 1]);
                accx0 = fmaf(v[j],     f0.x, accx0);
                accy0 = fmaf(v[j],     f0.y, accy0);
                accx1 = fmaf(v[j + 1], f1.x, accx1);
                accy1 = fmaf(v[j + 1], f1.y, accy1);
            }
        };

        load8(sA, vA, 0);
        for (int p = 8; p < npairs; p += 16) {
            load8(sB, vB, p);
            consume8(sA, vA);
            if (p + 8 < npairs) load8(sA, vA, p + 8);
            consume8(sB, vB);
        }
        if ((npairs >> 3) & 1) consume8(sA, vA);

        float accx = accx0 + accx1;
        float accy = accy0 + accy1;

        // merge even/odd halves (lanes L and L+16 hold partials for same batches)
        accx += __shfl_xor_sync(0xffffffffu, accx, 16);
        accy += __shfl_xor_sync(0xffffffffu, accy, 16);

        float sv = tanh_fast(hsel == 0 ? accx : accy);
        float sp = __shfl_xor_sync(0xffffffffu, sv, 16);   // partner's value

        if (hsel == 0) {
            nxt[r * (B_ / 2) + hl] = __floats2half2_rn(sv, sp);   // 64B coalesced
            tile[w][b0] = sv;
            tile[w][b1] = sp;
            if (t == T_ - 1) {
                g_final[r * B_ + b0] = sv;
                g_final[r * B_ + b1] = sp;
            }
        }
        __syncthreads();                         // all state/tile stores done

        // arrival: release orders all prior stores (cumulative via bar.sync)
        if (tid == 0) st_rel(&g_flag[blockIdx.x << 5], (unsigned)(t + 1));

        // ---- off-critical-path work while others arrive ----
        {   // transposed states write: half-warp writes 64B contiguous per batch
            int b  = w + ((lane >> 4) << 4);     // w or w+16
            int rr = lane & 15;
            __stcs(&states_out[(size_t)b * (T_ * R_) + (size_t)t * R_ + rbase + rr],
                   tile[rr][b]);
        }
        if (((t + 1) & (XBLK - 1)) == 0 && t + 1 < T_)
            refill_x(t + 1);                     // next 32-step x window

        // ---- wait: 128 threads poll 128 distinct flag lines ----
        if (tid < GRID) {
            while (ld_acq(&g_flag[tid << 5]) < (unsigned)(t + 1)) { }
        }
        __syncthreads();
    }
}

// ---------------- P3: output projection ----------------
__global__ void outproj_kernel(const float* __restrict__ wout,  // [O,R]
                               float* __restrict__ out) {       // [B*O]
    __shared__ float red[256];
    int pair = blockIdx.x;            // 0..95
    int b = pair / O_, o = pair - b * O_;

    float sum = 0.0f;
    for (int r = threadIdx.x; r < R_; r += blockDim.x)
        sum += g_final[r * B_ + b] * wout[o * R_ + r];

    red[threadIdx.x] = sum;
    __syncthreads();
    for (int s = 128; s > 0; s >>= 1) {
        if (threadIdx.x < s) red[threadIdx.x] += red[threadIdx.x + s];
        __syncthreads();
    }
    if (threadIdx.x == 0) out[b * O_ + o] = red[0];
}

// ---------------- launch ----------------
extern "C" void kernel_launch(void* const* d_in, const int* in_sizes, int n_in,
                              void* d_out, int out_size) {
    (void)in_sizes; (void)n_in; (void)out_size;
    const float* x     = (const float*)d_in[0];   // [B,T,I]
    const float* win   = (const float*)d_in[1];   // [R,I]
    const float* wres  = (const float*)d_in[2];   // [R,R]
    const float* wout  = (const float*)d_in[3];   // [O,R]
    const float* noise = (const float*)d_in[4];   // [B,R]
    float* out = (float*)d_out;                   // [B*O] then [B,T,R]

    prep_kernel<<<R_, 32>>>(wres);
    esn_kernel<<<GRID, NTHR>>>(x, win, noise, out + B_ * O_);
    outproj_kernel<<<B_ * O_, 256>>>(wout, out);
}